// round 16
// baseline (speedup 1.0000x reference)
#include <cuda_runtime.h>
#include <cuda_bf16.h>
#include <cstdint>

// Holt-Winters additive triple smoothing (gamma unused; season static).
// Carry v = (f, tr), f = smooth+trend:
//   e = y - (sea + f); tn = tr + ab*e; fn = f + al*e + tn; out = fn + sea
// Affine with constant M = [[1-c2, 1], [-ab, 1]], c2 = al+ab
// => blocked scan: chunk-local scan with v0=0 (parallel over (row,chunk)),
// then out_t += A11(dt)*f0 + A12(dt)*tr0, A = M^dt. Chunk 0 exact.
//
// R16 = R14 structure (16 rows x T in smem, 256 thr = (row,chunk), TMA bulk
// loads, 4096 blocks, occ ~69%) with the instruction stream stripped:
//  - season via doubled table s44[44] + per-chunk base pointer: zero
//    per-step index ALU, broadcast/distinct-bank LDS
//  - fixup: f4 = tid&127 is k-invariant -> chunk id + A-coeff float4s
//    hoisted out of the store loop
//  - 16 parallel TMA issuers (mbar arrive count 16)

constexpr int RB      = 16;    // rows per block
constexpr int NCH     = 16;    // chunks (T/32)
constexpr int C       = 32;    // steps per chunk
constexpr int THREADS = 256;   // RB * NCH
constexpr int STRIDE  = 516;   // smem row stride (floats)

__device__ __forceinline__ uint32_t smem_u32(const void* p) {
    return (uint32_t)__cvta_generic_to_shared(p);
}
__device__ __forceinline__ void mbar_init(uint32_t mbar, uint32_t count) {
    asm volatile("mbarrier.init.shared.b64 [%0], %1;" :: "r"(mbar), "r"(count) : "memory");
}
__device__ __forceinline__ void mbar_expect_tx(uint32_t mbar, uint32_t bytes) {
    asm volatile("mbarrier.arrive.expect_tx.shared.b64 _, [%0], %1;"
                 :: "r"(mbar), "r"(bytes) : "memory");
}
__device__ __forceinline__ void mbar_wait(uint32_t mbar, uint32_t parity) {
    asm volatile(
        "{\n\t.reg .pred P;\n"
        "W%=:\n\t"
        "mbarrier.try_wait.parity.shared.b64 P, [%0], %1;\n\t"
        "@P bra D%=;\n\t"
        "bra W%=;\n"
        "D%=:\n\t}"
        :: "r"(mbar), "r"(parity) : "memory");
}
__device__ __forceinline__ void bulk_ld(uint32_t dst, const void* src,
                                        uint32_t bytes, uint32_t mbar) {
    asm volatile(
        "cp.async.bulk.shared::cluster.global.mbarrier::complete_tx::bytes "
        "[%0], [%1], %2, [%3];"
        :: "r"(dst), "l"(src), "r"(bytes), "r"(mbar) : "memory");
}

__device__ __forceinline__ float hw_step_f(float y, float sea,
                                           float& f, float& tr,
                                           float al, float ab)
{
    float e  = y - (sea + f);
    float tn = fmaf(ab, e, tr);
    float fn = fmaf(al, e, f) + tn;
    tr = tn;
    f  = fn;
    return fn + sea;
}

__global__ __launch_bounds__(THREADS, 6)
void hw_kernel(const float* __restrict__ series,
               const int*   __restrict__ shifts,
               const float* __restrict__ alpha_p,
               const float* __restrict__ beta_p,
               const float* __restrict__ season_g,
               const float* __restrict__ init_trend_p,
               float* __restrict__ out,
               int T)
{
    __shared__ float    s_buf[RB * STRIDE];   // 33024 B, in-place y -> out
    __shared__ float    s44[44];              // doubled season table
    __shared__ float2   s_carry[RB * NCH];    // local end carries
    __shared__ float2   s_v0[RB * NCH];       // true chunk-start carries
    __shared__ float    s_A11[32];            // A11(dt), dt = i+1
    __shared__ float    s_A12[32];            // A12(dt)
    __shared__ float4   s_M32;                // full M^32
    __shared__ uint64_t s_mbar;

    const int tid  = threadIdx.x;
    const int r    = tid & (RB - 1);
    const int c    = tid >> 4;
    const int row0 = blockIdx.x * RB;

    const float alpha      = *alpha_p;
    const float beta       = *beta_p;
    const float init_trend = *init_trend_p;
    const float ab = alpha * beta;
    const float c2 = alpha + ab;

    const uint32_t mbar = smem_u32(&s_mbar);

    if (tid == 0) mbar_init(mbar, RB);        // one arrive per issuer
    if (tid < 44) s44[tid] = season_g[tid % 12];
    __syncthreads();                          // mbar + season visible

    // 16 parallel TMA issuers: each loads its contiguous 2KB row
    if (tid < RB) {
        mbar_expect_tx(mbar, (uint32_t)(T * 4));
        bulk_ld(smem_u32(&s_buf[tid * STRIDE]),
                series + (size_t)(row0 + tid) * T, T * 4, mbar);
    }

    if (tid == 0) {
        // A(dt) = M^dt, dt = 1..32 (row 0 only) + full M^32
        float p11 = 1.0f - c2, p12 = 1.0f, p21 = -ab, p22 = 1.0f;  // M^1
        s_A11[0] = p11; s_A12[0] = p12;
        for (int k = 1; k < C; ++k) {
            float n11 = (1.0f - c2) * p11 + p21;
            float n12 = (1.0f - c2) * p12 + p22;
            float n21 = -ab * p11 + p21;
            float n22 = -ab * p12 + p22;
            p11 = n11; p12 = n12; p21 = n21; p22 = n22;
            s_A11[k] = p11; s_A12[k] = p12;
        }
        s_M32 = make_float4(p11, p12, p21, p22);
    }

    mbar_wait(mbar, 0);                       // tile landed, visible

    // ---- pass A: local scan of chunk c on row r (in place) --------------
    {
        const int shift = shifts[row0 + r];
        int j0 = (c * C - shift) % 12; if (j0 < 0) j0 += 12;
        const float* ps = s44 + j0;           // step i uses ps[i], i<=31<44
        float4* rowp = (float4*)(s_buf + r * STRIDE + c * C);
        float f, tr;

        if (c == 0) {
            float4 y = rowp[0];
            f  = y.x + init_trend;            // state after t=0
            tr = init_trend;
            float4 o;
            o.x = f;                          // out[0] = y0 + init_trend
            o.y = hw_step_f(y.y, ps[1], f, tr, alpha, ab);
            o.z = hw_step_f(y.z, ps[2], f, tr, alpha, ab);
            o.w = hw_step_f(y.w, ps[3], f, tr, alpha, ab);
            rowp[0] = o;
            #pragma unroll
            for (int g = 1; g < C / 4; ++g) {
                float4 yy = rowp[g];
                float4 oo;
                oo.x = hw_step_f(yy.x, ps[g * 4 + 0], f, tr, alpha, ab);
                oo.y = hw_step_f(yy.y, ps[g * 4 + 1], f, tr, alpha, ab);
                oo.z = hw_step_f(yy.z, ps[g * 4 + 2], f, tr, alpha, ab);
                oo.w = hw_step_f(yy.w, ps[g * 4 + 3], f, tr, alpha, ab);
                rowp[g] = oo;
            }
        } else {
            f = 0.0f; tr = 0.0f;              // local scan, zero carry-in
            #pragma unroll
            for (int g = 0; g < C / 4; ++g) {
                float4 yy = rowp[g];
                float4 oo;
                oo.x = hw_step_f(yy.x, ps[g * 4 + 0], f, tr, alpha, ab);
                oo.y = hw_step_f(yy.y, ps[g * 4 + 1], f, tr, alpha, ab);
                oo.z = hw_step_f(yy.z, ps[g * 4 + 2], f, tr, alpha, ab);
                oo.w = hw_step_f(yy.w, ps[g * 4 + 3], f, tr, alpha, ab);
                rowp[g] = oo;
            }
        }
        s_carry[r * NCH + c] = make_float2(f, tr);
    }
    __syncthreads();

    // ---- carry propagation: one thread per row --------------------------
    if (tid < RB) {
        const int rr = tid;
        float4 M = s_M32;
        float2 v = s_carry[rr * NCH + 0];     // exact after chunk 0
        s_v0[rr * NCH + 0] = make_float2(0.0f, 0.0f);
        #pragma unroll
        for (int cc = 1; cc < NCH; ++cc) {
            s_v0[rr * NCH + cc] = v;
            float2 lc = s_carry[rr * NCH + cc];
            float nf = fmaf(M.x, v.x, fmaf(M.y, v.y, lc.x));
            float nt = fmaf(M.z, v.x, fmaf(M.w, v.y, lc.y));
            v = make_float2(nf, nt);
        }
    }
    __syncthreads();

    // ---- fix-up + coalesced store (k-invariant indices hoisted) ---------
    {
        const int t4 = T >> 2;                 // 128 float4 per row
        float4* __restrict__ dstv = (float4*)out;
        const int f4   = tid & 127;            // k-invariant!
        const int cc   = f4 >> 3;              // chunk of this float4
        const int i0   = (f4 & 7) * 4;         // in-chunk step base
        const int half = tid >> 7;             // 0 or 1
        const float4 A11 = *(const float4*)&s_A11[i0];
        const float4 A12 = *(const float4*)&s_A12[i0];
        const float* srcp = s_buf + f4 * 4;

        #pragma unroll
        for (int k = 0; k < (RB * 128) / THREADS; ++k) {   // 8 iters
            int rr = 2 * k + half;
            float4 v4 = *(const float4*)(srcp + rr * STRIDE);
            float2 v0 = s_v0[rr * NCH + cc];
            v4.x = fmaf(A11.x, v0.x, fmaf(A12.x, v0.y, v4.x));
            v4.y = fmaf(A11.y, v0.x, fmaf(A12.y, v0.y, v4.y));
            v4.z = fmaf(A11.z, v0.x, fmaf(A12.z, v0.y, v4.z));
            v4.w = fmaf(A11.w, v0.x, fmaf(A12.w, v0.y, v4.w));
            dstv[(size_t)(row0 + rr) * t4 + f4] = v4;
        }
    }
}

// Generic fallback (shape-safe) for any B/T/slen — reference formulation.
__global__ __launch_bounds__(256)
void hw_kernel_generic(const float* __restrict__ series,
                       const int*   __restrict__ shifts,
                       const float* __restrict__ alpha_p,
                       const float* __restrict__ beta_p,
                       const float* __restrict__ season_g,
                       const float* __restrict__ init_trend_p,
                       float* __restrict__ out,
                       int B, int T, int slen)
{
    int row = blockIdx.x * blockDim.x + threadIdx.x;
    if (row >= B) return;
    const float alpha = *alpha_p, beta = *beta_p;
    const float oma = 1.0f - alpha, omb = 1.0f - beta;
    int shift = shifts[row];
    int idx = (1 - shift) % slen; if (idx < 0) idx += slen;
    const float* src = series + (size_t)row * T;
    float* dst = out + (size_t)row * T;
    float smooth = src[0], trend = *init_trend_p;
    dst[0] = smooth + trend;
    for (int t = 1; t < T; ++t) {
        float sea = season_g[idx];
        idx = (idx + 1 == slen) ? 0 : idx + 1;
        float sn = alpha * (src[t] - sea) + oma * (smooth + trend);
        float tn = beta * (sn - smooth) + omb * trend;
        dst[t] = sn + tn + sea;
        smooth = sn; trend = tn;
    }
}

extern "C" void kernel_launch(void* const* d_in, const int* in_sizes, int n_in,
                              void* d_out, int out_size)
{
    // 0: series f32 [B*T]   1: shifts i32 [B]   2: alpha   3: beta
    // 4: gamma (unused)     5: init_season [SLEN]   6: init_trend   7: n_preds
    const float* series     = (const float*)d_in[0];
    const int*   shifts     = (const int*)  d_in[1];
    const float* alpha_p    = (const float*)d_in[2];
    const float* beta_p     = (const float*)d_in[3];
    const float* season     = (const float*)d_in[5];
    const float* init_trend = (const float*)d_in[6];
    float* out = (float*)d_out;

    int B    = in_sizes[1];
    int T    = in_sizes[0] / B;      // 512
    int slen = in_sizes[5];          // 12

    if (slen == 12 && T == 512 && (B % RB) == 0) {
        int blocks = B / RB;         // 4096
        hw_kernel<<<blocks, THREADS>>>(series, shifts, alpha_p, beta_p,
                                       season, init_trend, out, T);
    } else {
        int threads = 256;
        int blocks  = (B + threads - 1) / threads;
        hw_kernel_generic<<<blocks, threads>>>(series, shifts, alpha_p, beta_p,
                                               season, init_trend, out,
                                               B, T, slen);
    }
}